// round 9
// baseline (speedup 1.0000x reference)
#include <cuda_runtime.h>
#include <cuda_fp16.h>
#include <cstdint>

#define NN  100000
#define NE  1600000
#define NG  512
#define LL  1000
#define FXD 4
#define FXT 5
#define H   64
#define H2  128
#define NOUT 2
#define NBLK 98          // ceil(NN/1024) scan blocks
#define HISTB ((NE + 1023) / 1024)   // hist blocks (4 edges/thread)

// ---------------- scratch (zero at load; k_final re-zeroes what must be zero) ----------------
__device__ int    d_cnt[NN];           // in-degree (edges only; +1 self added logically)
__device__ int    d_off[NN];           // CSR offsets (incl. self)
__device__ int    d_cur[NN];           // bucket cursors
__device__ int    d_bsum[128];
__device__ int    d_bbase[128];
__device__ int    d_scan_done;
__device__ int    d_src[NE + NN];      // CSR source list (self at off[i], edges after)
__device__ float  d_dis[NN];
__device__ float4 d_xs[NN];            // dis[i] * x[i]
__device__ __half d_h1s[NN * H];       // dis[i] * relu-h1[i], fp16
__device__ int    d_gbits[NG * H2];    // pooled max(h2) as ordered int bits
__device__ float  d_tmax[NG * H];      // conv1d branch pooled output

__device__ __forceinline__ unsigned long long fma2(unsigned long long a,
                                                   unsigned long long b,
                                                   unsigned long long c) {
    unsigned long long d;
    asm("fma.rn.f32x2 %0, %1, %2, %3;" : "=l"(d) : "l"(a), "l"(b), "l"(c));
    return d;
}
__device__ __forceinline__ unsigned long long pack2(float a, float b) {
    unsigned long long d;
    asm("mov.b64 %0, {%1,%2};" : "=l"(d) : "f"(a), "f"(b));
    return d;
}
__device__ __forceinline__ float2 unpack2(unsigned long long a) {
    float2 r;
    asm("mov.b64 {%0,%1}, %2;" : "=f"(r.x), "=f"(r.y) : "l"(a));
    return r;
}

// ---------------- K1: blocks [0,NG): conv1d branch; blocks [NG,...): degree histogram ----
__global__ void k_histconv(const int* __restrict__ ei,
                           const float* __restrict__ target,
                           const float* __restrict__ Wc, const float* __restrict__ bc) {
    __shared__ __align__(16) char s_raw[25088];
    int tid = threadIdx.x;                    // 256

    if (blockIdx.x >= NG) {
        // ---- histogram: 4 edges per thread over the col half of ei ----
        int e = (blockIdx.x - NG) * 1024 + tid * 4;
        if (e + 4 <= NE) {
            int4 c4 = *(const int4*)(ei + NE + e);
            atomicAdd(&d_cnt[c4.x], 1);
            atomicAdd(&d_cnt[c4.y], 1);
            atomicAdd(&d_cnt[c4.z], 1);
            atomicAdd(&d_cnt[c4.w], 1);
        } else {
            for (int k = 0; k < 4 && e + k < NE; k++)
                atomicAdd(&d_cnt[ei[NE + e + k]], 1);
        }
        return;
    }

    // ---- conv1d branch ----
    float (*sh)[6] = (float(*)[6])s_raw;          // [LL][6], col 5 = zero pad
    float* red = (float*)(s_raw + 24000);         // [256]
    int g = blockIdx.x;
    const float* tg = target + (size_t)g * LL * FXT;
    for (int idx = tid; idx < LL * FXT; idx += 256) {
        int l = idx / FXT, i = idx - l * FXT;
        sh[l][i] = tg[idx];
    }
    for (int l = tid; l < LL; l += 256) sh[l][5] = 0.f;
    __syncthreads();

    int c   = tid & 63;
    int seg = tid >> 6;
    unsigned long long wk[3][3];
#pragma unroll
    for (int k = 0; k < 3; k++)
#pragma unroll
        for (int p = 0; p < 3; p++) {
            float w0 = Wc[c * 15 + (2 * p) * 3 + k];
            float w1 = (p < 2) ? Wc[c * 15 + (2 * p + 1) * 3 + k] : 0.f;
            wk[k][p] = pack2(w0, w1);
        }

    int start = seg * 250;
    int end = (seg == 3) ? (LL - 2) : (start + 250);
    float m = -3.4e38f;
    for (int l = start; l < end; l++) {
        unsigned long long a0 = 0ull, a1 = 0ull, a2 = 0ull;
#pragma unroll
        for (int k = 0; k < 3; k++) {
            const unsigned long long* row = (const unsigned long long*)&sh[l + k][0];
            a0 = fma2(row[0], wk[k][0], a0);
            a1 = fma2(row[1], wk[k][1], a1);
            a2 = fma2(row[2], wk[k][2], a2);
        }
        float2 f0 = unpack2(a0), f1 = unpack2(a1), f2 = unpack2(a2);
        m = fmaxf(m, (f0.x + f0.y) + (f1.x + f1.y) + (f2.x + f2.y));
    }
    red[tid] = m;
    __syncthreads();
    if (seg == 0) {
        m = fmaxf(fmaxf(red[c], red[64 + c]), fmaxf(red[128 + c], red[192 + c]));
        m += bc[c];
        d_tmax[g * H + c] = fmaxf(m, 0.f);
    }
}

// ---------------- K2: per-block sums + last-block scan of block sums ----------------
__global__ void k_scan12() {
    __shared__ int sh[256];
    __shared__ int lastflag;
    int b = blockIdx.x, tid = threadIdx.x;
    int base = b * 1024 + tid * 4;
    int s = 0;
#pragma unroll
    for (int k = 0; k < 4; k++) {
        int i = base + k;
        if (i < NN) s += d_cnt[i] + 1;
    }
    sh[tid] = s; __syncthreads();
    for (int o = 128; o; o >>= 1) { if (tid < o) sh[tid] += sh[tid + o]; __syncthreads(); }
    if (tid == 0) {
        d_bsum[b] = sh[0];
        __threadfence();
        int t = atomicAdd(&d_scan_done, 1);
        lastflag = (t == NBLK - 1);
    }
    __syncthreads();
    if (lastflag) {
        __threadfence();
        int v = (tid < NBLK) ? d_bsum[tid] : 0;
        sh[tid] = v; __syncthreads();
        for (int o = 1; o < 256; o <<= 1) {
            int y = (tid >= o) ? sh[tid - o] : 0;
            __syncthreads();
            sh[tid] += y;
            __syncthreads();
        }
        if (tid < NBLK) d_bbase[tid] = sh[tid] - v;   // exclusive
        if (tid == 0) d_scan_done = 0;
    }
}

// ---------------- K3: intra-block scan -> offsets, cursors(off+1), self entry, dis, xs ----
__global__ void k_scan3(const float* __restrict__ x) {
    __shared__ int tsum[256];
    int b = blockIdx.x, tid = threadIdx.x;
    int base = b * 1024 + tid * 4;
    int loc[4]; int s = 0;
#pragma unroll
    for (int k = 0; k < 4; k++) {
        int i = base + k;
        int v = (i < NN) ? (d_cnt[i] + 1) : 0;
        loc[k] = s; s += v;
    }
    tsum[tid] = s; __syncthreads();
    for (int o = 1; o < 256; o <<= 1) {
        int y = (tid >= o) ? tsum[tid - o] : 0;
        __syncthreads();
        tsum[tid] += y;
        __syncthreads();
    }
    int start = d_bbase[b] + tsum[tid] - s;   // exclusive
#pragma unroll
    for (int k = 0; k < 4; k++) {
        int i = base + k;
        if (i < NN) {
            int o = start + loc[k];
            d_off[i] = o;
            d_cur[i] = o + 1;                 // edges go after the self entry
            d_src[o] = i;                     // self loop
            float di = rsqrtf((float)(d_cnt[i] + 1));
            d_dis[i] = di;
            float4 xv = ((const float4*)x)[i];
            d_xs[i] = make_float4(di * xv.x, di * xv.y, di * xv.z, di * xv.w);
        }
    }
}

// ---------------- K4: bucket edges into CSR (4 edges/thread, int4) ----------------
__global__ void k_bucket(const int* __restrict__ ei) {
    int e = (blockIdx.x * blockDim.x + threadIdx.x) * 4;
    if (e >= NE) return;
    int4 r4 = *(const int4*)(ei + e);
    int4 c4 = *(const int4*)(ei + NE + e);
    d_src[atomicAdd(&d_cur[c4.x], 1)] = r4.x;
    d_src[atomicAdd(&d_cur[c4.y], 1)] = r4.y;
    d_src[atomicAdd(&d_cur[c4.z], 1)] = r4.z;
    d_src[atomicAdd(&d_cur[c4.w], 1)] = r4.w;
}

// ---------------- K5: layer-1 gather + W1 GEMM + relu, store h1s fp16 ----------------
__global__ void k_aggx_h1(const float* __restrict__ W1, const float* __restrict__ b1) {
    __shared__ float W1s[FXD][H];
    __shared__ float b1s[H];
    int tid = threadIdx.x;                    // 256
    if (tid < FXD * H) W1s[tid >> 6][tid & 63] = W1[tid];
    if (tid < H) b1s[tid] = b1[tid];
    __syncthreads();

    int i = blockIdx.x * 8 + (tid >> 5);      // node
    int lane = tid & 31;
    int off = d_off[i];
    int cnt = d_cnt[i] + 1;
    float4 acc = make_float4(0.f, 0.f, 0.f, 0.f);
    for (int j = lane; j < cnt; j += 32) {
        int r = d_src[off + j];
        float4 t = d_xs[r];
        acc.x += t.x; acc.y += t.y; acc.z += t.z; acc.w += t.w;
    }
#pragma unroll
    for (int o = 16; o; o >>= 1) {
        acc.x += __shfl_xor_sync(0xffffffffu, acc.x, o);
        acc.y += __shfl_xor_sync(0xffffffffu, acc.y, o);
        acc.z += __shfl_xor_sync(0xffffffffu, acc.z, o);
        acc.w += __shfl_xor_sync(0xffffffffu, acc.w, o);
    }
    float di = d_dis[i];
    float4 v = make_float4(di * acc.x, di * acc.y, di * acc.z, di * acc.w);
    int f0 = 2 * lane;
    float h0 = b1s[f0]   + v.x * W1s[0][f0]   + v.y * W1s[1][f0]   + v.z * W1s[2][f0]   + v.w * W1s[3][f0];
    float h1 = b1s[f0+1] + v.x * W1s[0][f0+1] + v.y * W1s[1][f0+1] + v.z * W1s[2][f0+1] + v.w * W1s[3][f0+1];
    h0 = fmaxf(h0, 0.f) * di;
    h1 = fmaxf(h1, 0.f) * di;
    ((__half2*)d_h1s)[i * 32 + lane] = __floats2half2_rn(h0, h1);
}

// ---------------- K6: balanced layer-2 gather + W2 GEMM + pooled max (16 nodes/block) ----
__global__ void k_fused(const float* __restrict__ W2, const float* __restrict__ b2,
                        const int* __restrict__ batch) {
    __shared__ __align__(16) float vt[H][20];   // [k][node], 16 nodes + pad
    __shared__ int soff[17];
    __shared__ float dd[16];
    int tid = threadIdx.x;                      // 256
    int i0 = blockIdx.x * 16;                   // 6250 blocks

    for (int idx = tid; idx < H * 20; idx += 256) ((float*)vt)[idx] = 0.f;
    if (tid < 17) soff[tid] = (i0 + tid < NN) ? d_off[i0 + tid] : (NE + NN);
    if (tid < 16) dd[tid] = d_dis[i0 + tid];
    __syncthreads();

    {   // phase 1: balanced edge walk, 8 warps split the block's contiguous CSR range
        int w = tid >> 5;
        int lane = tid & 31;
        int eb = soff[0], ee = soff[16];
        int per = ((ee - eb) + 7) >> 3;
        int e = eb + w * per;
        int wend = min(e + per, ee);
        const __half2* h1s2 = (const __half2*)d_h1s;
        if (e < wend) {
            int n = 0;
            while (soff[n + 1] <= e) n++;
            while (e < wend) {
                int seg_end = min(wend, soff[n + 1]);
                float ax = 0.f, ay = 0.f;
                int t = e;
                for (; t + 4 <= seg_end; t += 4) {
                    int r0 = d_src[t], r1 = d_src[t + 1];
                    int r2 = d_src[t + 2], r3 = d_src[t + 3];
                    float2 f0 = __half22float2(h1s2[r0 * 32 + lane]);
                    float2 f1 = __half22float2(h1s2[r1 * 32 + lane]);
                    float2 f2 = __half22float2(h1s2[r2 * 32 + lane]);
                    float2 f3 = __half22float2(h1s2[r3 * 32 + lane]);
                    ax += (f0.x + f1.x) + (f2.x + f3.x);
                    ay += (f0.y + f1.y) + (f2.y + f3.y);
                }
                for (; t < seg_end; t++) {
                    int r0 = d_src[t];
                    float2 f0 = __half22float2(h1s2[r0 * 32 + lane]);
                    ax += f0.x; ay += f0.y;
                }
                atomicAdd(&vt[2 * lane][n], ax);
                atomicAdd(&vt[2 * lane + 1][n], ay);
                e = seg_end; n++;
            }
        }
    }
    __syncthreads();

    // scale by dis of destination node
    for (int idx = tid; idx < H * 16; idx += 256) {
        int k = idx >> 4, n = idx & 15;
        vt[k][n] *= dd[n];
    }
    __syncthreads();

    // phase 2: GEMM, f = tid&127, half = tid>>7 handles 8 nodes
    int f = tid & 127;
    int half = tid >> 7;
    float bb = b2[f];
    unsigned long long a01 = pack2(bb, bb), a23 = a01, a45 = a01, a67 = a01;
#pragma unroll
    for (int k = 0; k < H; k++) {
        float wv = __ldg(&W2[k * H2 + f]);
        unsigned long long wd = pack2(wv, wv);
        const ulonglong2* P = (const ulonglong2*)&vt[k][half * 8];
        ulonglong2 p0 = P[0];
        ulonglong2 p1 = P[1];
        a01 = fma2(p0.x, wd, a01);
        a23 = fma2(p0.y, wd, a23);
        a45 = fma2(p1.x, wd, a45);
        a67 = fma2(p1.y, wd, a67);
    }
    float2 r01 = unpack2(a01), r23 = unpack2(a23), r45 = unpack2(a45), r67 = unpack2(a67);
    float h[8] = { r01.x, r01.y, r23.x, r23.y, r45.x, r45.y, r67.x, r67.y };

    int bA = batch[i0];
    int bB = batch[i0 + 15];
    float mA = -1.f, mB = -1.f;
#pragma unroll
    for (int n = 0; n < 8; n++) {
        float hv = fmaxf(h[n], 0.f);
        if (batch[i0 + half * 8 + n] == bA) mA = fmaxf(mA, hv); else mB = fmaxf(mB, hv);
    }
    atomicMax(&d_gbits[bA * H2 + f], __float_as_int(mA));   // -1 bits are negative: no-op
    if (bB != bA) atomicMax(&d_gbits[bB * H2 + f], __float_as_int(mB));
}

// ---------------- K7: fused final MLPs + scratch re-zero for graph replay ----------------
__global__ void k_final(const float* __restrict__ Wg, const float* __restrict__ bg,
                        const float* __restrict__ Wt, const float* __restrict__ bt,
                        const float* __restrict__ Wf, const float* __restrict__ bf,
                        const float* __restrict__ Wo, const float* __restrict__ bo,
                        float* __restrict__ out) {
    __shared__ float sg[H2], st[H], sxc[H2], sy[H];
    int g = blockIdx.x;
    int f = threadIdx.x;                    // 64
    sg[f]      = __int_as_float(d_gbits[g * H2 + f]);
    sg[H + f]  = __int_as_float(d_gbits[g * H2 + H + f]);
    st[f]      = d_tmax[g * H + f];
    // re-zero own gbits slice for next replay (only this block reads it)
    d_gbits[g * H2 + f] = 0;
    d_gbits[g * H2 + H + f] = 0;
    // re-zero d_cnt strided (no kernel after this one reads it)
    for (int i = g * 64 + f; i < NN; i += NG * 64) d_cnt[i] = 0;
    __syncthreads();

    float gg = bg[f];
#pragma unroll 8
    for (int j = 0; j < H2; j++) gg += sg[j] * Wg[j * H + f];
    float tt = bt[f];
#pragma unroll 8
    for (int j = 0; j < H; j++) tt += st[j] * Wt[j * H + f];
    sxc[f] = gg;
    sxc[H + f] = tt;
    __syncthreads();

    float y = bf[f];
#pragma unroll 8
    for (int j = 0; j < H2; j++) y += sxc[j] * Wf[j * H + f];
    sy[f] = fmaxf(y, 0.f);
    __syncthreads();

    if (f < NOUT) {
        float o = bo[f];
#pragma unroll 8
        for (int j = 0; j < H; j++) o += sy[j] * Wo[j * NOUT + f];
        out[g * NOUT + f] = o;
    }
}

// ---------------- launch ----------------
extern "C" void kernel_launch(void* const* d_in, const int* in_sizes, int n_in,
                              void* d_out, int out_size) {
    const float* x      = (const float*)d_in[0];
    const int*   ei     = (const int*)d_in[1];
    const int*   batch  = (const int*)d_in[2];
    const float* target = (const float*)d_in[3];
    const float* W1 = (const float*)d_in[4];
    const float* b1 = (const float*)d_in[5];
    const float* W2 = (const float*)d_in[6];
    const float* b2 = (const float*)d_in[7];
    const float* Wg = (const float*)d_in[8];
    const float* bg = (const float*)d_in[9];
    const float* Wc = (const float*)d_in[10];
    const float* bc = (const float*)d_in[11];
    const float* Wt = (const float*)d_in[12];
    const float* bt = (const float*)d_in[13];
    const float* Wf = (const float*)d_in[14];
    const float* bf = (const float*)d_in[15];
    const float* Wo = (const float*)d_in[16];
    const float* bo = (const float*)d_in[17];
    float* out = (float*)d_out;

    k_histconv<<<NG + HISTB, 256>>>(ei, target, Wc, bc);
    k_scan12<<<NBLK, 256>>>();
    k_scan3<<<NBLK, 256>>>(x);
    k_bucket<<<(NE / 4 + 255) / 256, 256>>>(ei);
    k_aggx_h1<<<NN / 8, 256>>>(W1, b1);
    k_fused<<<NN / 16, 256>>>(W2, b2, batch);
    k_final<<<NG, 64>>>(Wg, bg, Wt, bt, Wf, bf, Wo, bo, out);
}

// round 14
// speedup vs baseline: 1.1345x; 1.1345x over previous
#include <cuda_runtime.h>
#include <cuda_fp16.h>
#include <cstdint>

#define NN  100000
#define NE  1600000
#define NG  512
#define LL  1000
#define FXD 4
#define FXT 5
#define H   64
#define H2  128
#define NOUT 2
#define NBLK 98          // ceil(NN/1024) scan blocks (one wave, <=148 SMs)
#define HISTB ((NE + 1023) / 1024)   // hist blocks (4 edges/thread)

// ---------------- scratch (zero at load; k_final re-zeroes what must be zero) ----------------
__device__ int    d_cnt[NN];           // in-degree (edges only; +1 self added logically)
__device__ int    d_off[NN];           // CSR offsets (incl. self)
__device__ int    d_cur[NN];           // bucket cursors
__device__ int    d_bsum[NBLK];        // block totals; nonzero doubles as ready flag
__device__ int    d_src[NE + NN];      // CSR source list (self at off[i], edges after)
__device__ float  d_dis[NN];
__device__ float4 d_xs[NN];            // dis[i] * x[i]
__device__ __half d_h1s[NN * H];       // dis[i] * relu-h1[i], fp16
__device__ int    d_gbits[NG * H2];    // pooled max(h2) as ordered int bits
__device__ float  d_tmax[NG * H];      // conv1d branch pooled output

__device__ __forceinline__ unsigned long long fma2(unsigned long long a,
                                                   unsigned long long b,
                                                   unsigned long long c) {
    unsigned long long d;
    asm("fma.rn.f32x2 %0, %1, %2, %3;" : "=l"(d) : "l"(a), "l"(b), "l"(c));
    return d;
}
__device__ __forceinline__ unsigned long long pack2(float a, float b) {
    unsigned long long d;
    asm("mov.b64 %0, {%1,%2};" : "=l"(d) : "f"(a), "f"(b));
    return d;
}
__device__ __forceinline__ float2 unpack2(unsigned long long a) {
    float2 r;
    asm("mov.b64 {%0,%1}, %2;" : "=f"(r.x), "=f"(r.y) : "l"(a));
    return r;
}

// ---------------- K1: blocks [0,NG): conv1d branch; blocks [NG,...): degree histogram ----
__global__ void k_histconv(const int* __restrict__ ei,
                           const float* __restrict__ target,
                           const float* __restrict__ Wc, const float* __restrict__ bc) {
    __shared__ __align__(16) char s_raw[25088];
    int tid = threadIdx.x;                    // 256

    if (blockIdx.x >= NG) {
        // ---- histogram: 4 edges per thread over the col half of ei ----
        int e = (blockIdx.x - NG) * 1024 + tid * 4;
        if (e + 4 <= NE) {
            int4 c4 = *(const int4*)(ei + NE + e);
            atomicAdd(&d_cnt[c4.x], 1);
            atomicAdd(&d_cnt[c4.y], 1);
            atomicAdd(&d_cnt[c4.z], 1);
            atomicAdd(&d_cnt[c4.w], 1);
        } else {
            for (int k = 0; k < 4 && e + k < NE; k++)
                atomicAdd(&d_cnt[ei[NE + e + k]], 1);
        }
        return;
    }

    // ---- conv1d branch ----
    float (*sh)[6] = (float(*)[6])s_raw;          // [LL][6], col 5 = zero pad
    float* red = (float*)(s_raw + 24000);         // [256]
    int g = blockIdx.x;
    const float* tg = target + (size_t)g * LL * FXT;
    for (int idx = tid; idx < LL * FXT; idx += 256) {
        int l = idx / FXT, i = idx - l * FXT;
        sh[l][i] = tg[idx];
    }
    for (int l = tid; l < LL; l += 256) sh[l][5] = 0.f;
    __syncthreads();

    int c   = tid & 63;
    int seg = tid >> 6;
    unsigned long long wk[3][3];
#pragma unroll
    for (int k = 0; k < 3; k++)
#pragma unroll
        for (int p = 0; p < 3; p++) {
            float w0 = Wc[c * 15 + (2 * p) * 3 + k];
            float w1 = (p < 2) ? Wc[c * 15 + (2 * p + 1) * 3 + k] : 0.f;
            wk[k][p] = pack2(w0, w1);
        }

    int start = seg * 250;
    int end = (seg == 3) ? (LL - 2) : (start + 250);
    float m = -3.4e38f;
    for (int l = start; l < end; l++) {
        unsigned long long a0 = 0ull, a1 = 0ull, a2 = 0ull;
#pragma unroll
        for (int k = 0; k < 3; k++) {
            const unsigned long long* row = (const unsigned long long*)&sh[l + k][0];
            a0 = fma2(row[0], wk[k][0], a0);
            a1 = fma2(row[1], wk[k][1], a1);
            a2 = fma2(row[2], wk[k][2], a2);
        }
        float2 f0 = unpack2(a0), f1 = unpack2(a1), f2 = unpack2(a2);
        m = fmaxf(m, (f0.x + f0.y) + (f1.x + f1.y) + (f2.x + f2.y));
    }
    red[tid] = m;
    __syncthreads();
    if (seg == 0) {
        m = fmaxf(fmaxf(red[c], red[64 + c]), fmaxf(red[128 + c], red[192 + c]));
        m += bc[c];
        d_tmax[g * H + c] = fmaxf(m, 0.f);
    }
}

// ---------------- K2: single-pass scan (decoupled prefix) -> offsets, cursors, self, dis, xs
__global__ void k_scan(const float* __restrict__ x) {
    __shared__ int tsum[256];
    __shared__ int sh_base;
    int b = blockIdx.x, tid = threadIdx.x;
    int base4 = b * 1024 + tid * 4;
    int loc[4]; int s = 0;
#pragma unroll
    for (int k = 0; k < 4; k++) {
        int i = base4 + k;
        int v = (i < NN) ? (d_cnt[i] + 1) : 0;
        loc[k] = s; s += v;
    }
    tsum[tid] = s; __syncthreads();
    for (int o = 1; o < 256; o <<= 1) {
        int y = (tid >= o) ? tsum[tid - o] : 0;
        __syncthreads();
        tsum[tid] += y;
        __syncthreads();
    }
    // publish this block's total (nonzero: every node contributes >=1)
    if (tid == 0) *(volatile int*)&d_bsum[b] = tsum[255];
    // warp 0 spins on predecessors to get exclusive base
    if (tid < 32) {
        int acc = 0;
        for (int p = tid; p < b; p += 32) {
            int v;
            do { v = *(volatile int*)&d_bsum[p]; } while (v == 0);
            acc += v;
        }
#pragma unroll
        for (int o = 16; o; o >>= 1) acc += __shfl_xor_sync(0xffffffffu, acc, o);
        if (tid == 0) sh_base = acc;
    }
    __syncthreads();
    int start = sh_base + tsum[tid] - s;      // exclusive prefix for this thread's 4 nodes
#pragma unroll
    for (int k = 0; k < 4; k++) {
        int i = base4 + k;
        if (i < NN) {
            int o = start + loc[k];
            d_off[i] = o;
            d_cur[i] = o + 1;                 // edges go after the self entry
            d_src[o] = i;                     // self loop
            float di = rsqrtf((float)(d_cnt[i] + 1));
            d_dis[i] = di;
            float4 xv = ((const float4*)x)[i];
            d_xs[i] = make_float4(di * xv.x, di * xv.y, di * xv.z, di * xv.w);
        }
    }
}

// ---------------- K3: bucket edges into CSR ----------------
__global__ void k_bucket(const int* __restrict__ ei) {
    int e = blockIdx.x * blockDim.x + threadIdx.x;
    if (e >= NE) return;
    int r = ei[e];
    int c = ei[NE + e];
    int pos = atomicAdd(&d_cur[c], 1);
    d_src[pos] = r;
}

// ---------------- K4: layer-1 gather + W1 GEMM + relu, store h1s fp16 ----------------
__global__ void k_aggx_h1(const float* __restrict__ W1, const float* __restrict__ b1) {
    __shared__ float W1s[FXD][H];
    __shared__ float b1s[H];
    int tid = threadIdx.x;                    // 256
    if (tid < FXD * H) W1s[tid >> 6][tid & 63] = W1[tid];
    if (tid < H) b1s[tid] = b1[tid];
    __syncthreads();

    int i = blockIdx.x * 8 + (tid >> 5);      // node
    int lane = tid & 31;
    int off = d_off[i];
    int cnt = d_cnt[i] + 1;
    float4 acc = make_float4(0.f, 0.f, 0.f, 0.f);
    for (int j = lane; j < cnt; j += 32) {
        int r = d_src[off + j];
        float4 t = d_xs[r];
        acc.x += t.x; acc.y += t.y; acc.z += t.z; acc.w += t.w;
    }
#pragma unroll
    for (int o = 16; o; o >>= 1) {
        acc.x += __shfl_xor_sync(0xffffffffu, acc.x, o);
        acc.y += __shfl_xor_sync(0xffffffffu, acc.y, o);
        acc.z += __shfl_xor_sync(0xffffffffu, acc.z, o);
        acc.w += __shfl_xor_sync(0xffffffffu, acc.w, o);
    }
    float di = d_dis[i];
    float4 v = make_float4(di * acc.x, di * acc.y, di * acc.z, di * acc.w);
    int f0 = 2 * lane;
    float h0 = b1s[f0]   + v.x * W1s[0][f0]   + v.y * W1s[1][f0]   + v.z * W1s[2][f0]   + v.w * W1s[3][f0];
    float h1 = b1s[f0+1] + v.x * W1s[0][f0+1] + v.y * W1s[1][f0+1] + v.z * W1s[2][f0+1] + v.w * W1s[3][f0+1];
    h0 = fmaxf(h0, 0.f) * di;
    h1 = fmaxf(h1, 0.f) * di;
    ((__half2*)d_h1s)[i * 32 + lane] = __floats2half2_rn(h0, h1);
}

// ---------------- K5: layer-2 gather + W2 GEMM + pooled max (16 nodes/block) ----------
__global__ void k_fused(const float* __restrict__ W2, const float* __restrict__ b2,
                        const int* __restrict__ batch) {
    __shared__ __align__(16) float vt[H][20];   // [k][node], 16 nodes + pad
    int tid = threadIdx.x;                      // 256
    int i0 = blockIdx.x * 16;                   // 6250 blocks

    {   // phase 1: warp per 2 nodes, 4-wide unrolled gather
        int w = tid >> 5;
        int lane = tid & 31;
        const __half2* h1s2 = (const __half2*)d_h1s;
#pragma unroll
        for (int sub = 0; sub < 2; sub++) {
            int n = w * 2 + sub;
            int i = i0 + n;
            int off = d_off[i];
            int cnt = d_cnt[i] + 1;
            float ax0 = 0.f, ay0 = 0.f, ax1 = 0.f, ay1 = 0.f;
            int t = 0;
            for (; t + 4 <= cnt; t += 4) {
                int r0 = __ldg(&d_src[off + t]);
                int r1 = __ldg(&d_src[off + t + 1]);
                int r2 = __ldg(&d_src[off + t + 2]);
                int r3 = __ldg(&d_src[off + t + 3]);
                float2 f0 = __half22float2(h1s2[r0 * 32 + lane]);
                float2 f1 = __half22float2(h1s2[r1 * 32 + lane]);
                float2 f2 = __half22float2(h1s2[r2 * 32 + lane]);
                float2 f3 = __half22float2(h1s2[r3 * 32 + lane]);
                ax0 += f0.x + f2.x; ay0 += f0.y + f2.y;
                ax1 += f1.x + f3.x; ay1 += f1.y + f3.y;
            }
            for (; t < cnt; t++) {
                int r0 = __ldg(&d_src[off + t]);
                float2 f0 = __half22float2(h1s2[r0 * 32 + lane]);
                ax0 += f0.x; ay0 += f0.y;
            }
            float di = d_dis[i];
            vt[2 * lane][n]     = di * (ax0 + ax1);
            vt[2 * lane + 1][n] = di * (ay0 + ay1);
        }
    }
    __syncthreads();

    // phase 2: GEMM, f = tid&127, half = tid>>7 handles 8 nodes
    int f = tid & 127;
    int half = tid >> 7;
    float bb = b2[f];
    unsigned long long a01 = pack2(bb, bb), a23 = a01, a45 = a01, a67 = a01;
#pragma unroll
    for (int k = 0; k < H; k++) {
        float wv = __ldg(&W2[k * H2 + f]);
        unsigned long long wd = pack2(wv, wv);
        const ulonglong2* P = (const ulonglong2*)&vt[k][half * 8];
        ulonglong2 p0 = P[0];
        ulonglong2 p1 = P[1];
        a01 = fma2(p0.x, wd, a01);
        a23 = fma2(p0.y, wd, a23);
        a45 = fma2(p1.x, wd, a45);
        a67 = fma2(p1.y, wd, a67);
    }
    float2 r01 = unpack2(a01), r23 = unpack2(a23), r45 = unpack2(a45), r67 = unpack2(a67);
    float h[8] = { r01.x, r01.y, r23.x, r23.y, r45.x, r45.y, r67.x, r67.y };

    int bA = batch[i0];
    int bB = batch[i0 + 15];
    float mA = -1.f, mB = -1.f;
#pragma unroll
    for (int n = 0; n < 8; n++) {
        float hv = fmaxf(h[n], 0.f);
        if (batch[i0 + half * 8 + n] == bA) mA = fmaxf(mA, hv); else mB = fmaxf(mB, hv);
    }
    atomicMax(&d_gbits[bA * H2 + f], __float_as_int(mA));   // -1 bits are negative: no-op
    if (bB != bA) atomicMax(&d_gbits[bB * H2 + f], __float_as_int(mB));
}

// ---------------- K6: fused final MLPs + scratch re-zero for graph replay ----------------
__global__ void k_final(const float* __restrict__ Wg, const float* __restrict__ bg,
                        const float* __restrict__ Wt, const float* __restrict__ bt,
                        const float* __restrict__ Wf, const float* __restrict__ bf,
                        const float* __restrict__ Wo, const float* __restrict__ bo,
                        float* __restrict__ out) {
    __shared__ float sg[H2], st[H], sxc[H2], sy[H];
    int g = blockIdx.x;
    int f = threadIdx.x;                    // 64
    sg[f]      = __int_as_float(d_gbits[g * H2 + f]);
    sg[H + f]  = __int_as_float(d_gbits[g * H2 + H + f]);
    st[f]      = d_tmax[g * H + f];
    // re-zero own gbits slice for next replay (only this block reads it)
    d_gbits[g * H2 + f] = 0;
    d_gbits[g * H2 + H + f] = 0;
    // re-zero d_cnt strided and d_bsum (scan flags) for next replay
    for (int i = g * 64 + f; i < NN; i += NG * 64) d_cnt[i] = 0;
    {
        int gi = g * 64 + f;
        if (gi < NBLK) d_bsum[gi] = 0;
    }
    __syncthreads();

    float gg = bg[f];
#pragma unroll 8
    for (int j = 0; j < H2; j++) gg += sg[j] * Wg[j * H + f];
    float tt = bt[f];
#pragma unroll 8
    for (int j = 0; j < H; j++) tt += st[j] * Wt[j * H + f];
    sxc[f] = gg;
    sxc[H + f] = tt;
    __syncthreads();

    float y = bf[f];
#pragma unroll 8
    for (int j = 0; j < H2; j++) y += sxc[j] * Wf[j * H + f];
    sy[f] = fmaxf(y, 0.f);
    __syncthreads();

    if (f < NOUT) {
        float o = bo[f];
#pragma unroll 8
        for (int j = 0; j < H; j++) o += sy[j] * Wo[j * NOUT + f];
        out[g * NOUT + f] = o;
    }
}

// ---------------- launch ----------------
extern "C" void kernel_launch(void* const* d_in, const int* in_sizes, int n_in,
                              void* d_out, int out_size) {
    const float* x      = (const float*)d_in[0];
    const int*   ei     = (const int*)d_in[1];
    const int*   batch  = (const int*)d_in[2];
    const float* target = (const float*)d_in[3];
    const float* W1 = (const float*)d_in[4];
    const float* b1 = (const float*)d_in[5];
    const float* W2 = (const float*)d_in[6];
    const float* b2 = (const float*)d_in[7];
    const float* Wg = (const float*)d_in[8];
    const float* bg = (const float*)d_in[9];
    const float* Wc = (const float*)d_in[10];
    const float* bc = (const float*)d_in[11];
    const float* Wt = (const float*)d_in[12];
    const float* bt = (const float*)d_in[13];
    const float* Wf = (const float*)d_in[14];
    const float* bf = (const float*)d_in[15];
    const float* Wo = (const float*)d_in[16];
    const float* bo = (const float*)d_in[17];
    float* out = (float*)d_out;

    k_histconv<<<NG + HISTB, 256>>>(ei, target, Wc, bc);
    k_scan<<<NBLK, 256>>>(x);
    k_bucket<<<(NE + 255) / 256, 256>>>(ei);
    k_aggx_h1<<<NN / 8, 256>>>(W1, b1);
    k_fused<<<NN / 16, 256>>>(W2, b2, batch);
    k_final<<<NG, 64>>>(Wg, bg, Wt, bt, Wf, bf, Wo, bo, out);
}

// round 15
// speedup vs baseline: 1.1724x; 1.0335x over previous
#include <cuda_runtime.h>
#include <cuda_fp16.h>
#include <cstdint>

#define NN  100000
#define NE  1600000
#define NG  512
#define LL  1000
#define FXD 4
#define FXT 5
#define H   64
#define H2  128
#define NOUT 2
#define NBLK 98          // ceil(NN/1024) scan blocks (one wave, <=148 SMs)
#define HISTB ((NE + 1023) / 1024)   // hist blocks (4 edges/thread)

// ---------------- scratch (zero at load; k_final re-zeroes what must be zero) ----------------
__device__ int    d_cnt[NN];           // in-degree (edges only; +1 self added logically)
__device__ int    d_off[NN];           // CSR offsets (incl. self)
__device__ int    d_cur[NN];           // bucket cursors
__device__ int    d_bsum[NBLK];        // block totals; nonzero doubles as ready flag
__device__ int    d_src[NE + NN];      // CSR source list (self at off[i], edges after)
__device__ float  d_dis[NN];
__device__ float4 d_xs[NN];            // dis[i] * x[i]
__device__ __half d_h1s[NN * H];       // dis[i] * relu-h1[i], fp16
__device__ int    d_gbits[NG * H2];    // pooled max(h2) as ordered int bits
__device__ float  d_tmax[NG * H];      // conv1d branch pooled output

__device__ __forceinline__ unsigned long long fma2(unsigned long long a,
                                                   unsigned long long b,
                                                   unsigned long long c) {
    unsigned long long d;
    asm("fma.rn.f32x2 %0, %1, %2, %3;" : "=l"(d) : "l"(a), "l"(b), "l"(c));
    return d;
}
__device__ __forceinline__ unsigned long long pack2(float a, float b) {
    unsigned long long d;
    asm("mov.b64 %0, {%1,%2};" : "=l"(d) : "f"(a), "f"(b));
    return d;
}
__device__ __forceinline__ float2 unpack2(unsigned long long a) {
    float2 r;
    asm("mov.b64 {%0,%1}, %2;" : "=f"(r.x), "=f"(r.y) : "l"(a));
    return r;
}

// ---------------- K1: blocks [0,NG): conv1d branch; blocks [NG,...): degree histogram ----
__global__ void k_histconv(const int* __restrict__ ei,
                           const float* __restrict__ target,
                           const float* __restrict__ Wc, const float* __restrict__ bc) {
    __shared__ __align__(16) char s_raw[25088];
    int tid = threadIdx.x;                    // 256

    if (blockIdx.x >= NG) {
        // ---- histogram: 4 edges per thread over the col half of ei ----
        int e = (blockIdx.x - NG) * 1024 + tid * 4;
        if (e + 4 <= NE) {
            int4 c4 = *(const int4*)(ei + NE + e);
            atomicAdd(&d_cnt[c4.x], 1);
            atomicAdd(&d_cnt[c4.y], 1);
            atomicAdd(&d_cnt[c4.z], 1);
            atomicAdd(&d_cnt[c4.w], 1);
        } else {
            for (int k = 0; k < 4 && e + k < NE; k++)
                atomicAdd(&d_cnt[ei[NE + e + k]], 1);
        }
        return;
    }

    // ---- conv1d branch ----
    float (*sh)[6] = (float(*)[6])s_raw;          // [LL][6], col 5 = zero pad
    float* red = (float*)(s_raw + 24000);         // [256]
    int g = blockIdx.x;
    const float* tg = target + (size_t)g * LL * FXT;
    for (int idx = tid; idx < LL * FXT; idx += 256) {
        int l = idx / FXT, i = idx - l * FXT;
        sh[l][i] = tg[idx];
    }
    for (int l = tid; l < LL; l += 256) sh[l][5] = 0.f;
    __syncthreads();

    int c   = tid & 63;
    int seg = tid >> 6;
    unsigned long long wk[3][3];
#pragma unroll
    for (int k = 0; k < 3; k++)
#pragma unroll
        for (int p = 0; p < 3; p++) {
            float w0 = Wc[c * 15 + (2 * p) * 3 + k];
            float w1 = (p < 2) ? Wc[c * 15 + (2 * p + 1) * 3 + k] : 0.f;
            wk[k][p] = pack2(w0, w1);
        }

    int start = seg * 250;
    int end = (seg == 3) ? (LL - 2) : (start + 250);
    float m = -3.4e38f;
    for (int l = start; l < end; l++) {
        unsigned long long a0 = 0ull, a1 = 0ull, a2 = 0ull;
#pragma unroll
        for (int k = 0; k < 3; k++) {
            const unsigned long long* row = (const unsigned long long*)&sh[l + k][0];
            a0 = fma2(row[0], wk[k][0], a0);
            a1 = fma2(row[1], wk[k][1], a1);
            a2 = fma2(row[2], wk[k][2], a2);
        }
        float2 f0 = unpack2(a0), f1 = unpack2(a1), f2 = unpack2(a2);
        m = fmaxf(m, (f0.x + f0.y) + (f1.x + f1.y) + (f2.x + f2.y));
    }
    red[tid] = m;
    __syncthreads();
    if (seg == 0) {
        m = fmaxf(fmaxf(red[c], red[64 + c]), fmaxf(red[128 + c], red[192 + c]));
        m += bc[c];
        d_tmax[g * H + c] = fmaxf(m, 0.f);
    }
}

// ---------------- K2: single-pass scan (decoupled prefix) -> offsets, cursors, self, dis, xs
__global__ void k_scan(const float* __restrict__ x) {
    __shared__ int tsum[256];
    __shared__ int sh_base;
    int b = blockIdx.x, tid = threadIdx.x;
    int base4 = b * 1024 + tid * 4;
    int loc[4]; int s = 0;
#pragma unroll
    for (int k = 0; k < 4; k++) {
        int i = base4 + k;
        int v = (i < NN) ? (d_cnt[i] + 1) : 0;
        loc[k] = s; s += v;
    }
    tsum[tid] = s; __syncthreads();
    for (int o = 1; o < 256; o <<= 1) {
        int y = (tid >= o) ? tsum[tid - o] : 0;
        __syncthreads();
        tsum[tid] += y;
        __syncthreads();
    }
    // publish this block's total (nonzero: every node contributes >=1)
    if (tid == 0) *(volatile int*)&d_bsum[b] = tsum[255];
    // warp 0 spins on predecessors to get exclusive base
    if (tid < 32) {
        int acc = 0;
        for (int p = tid; p < b; p += 32) {
            int v;
            do { v = *(volatile int*)&d_bsum[p]; } while (v == 0);
            acc += v;
        }
#pragma unroll
        for (int o = 16; o; o >>= 1) acc += __shfl_xor_sync(0xffffffffu, acc, o);
        if (tid == 0) sh_base = acc;
    }
    __syncthreads();
    int start = sh_base + tsum[tid] - s;      // exclusive prefix for this thread's 4 nodes
#pragma unroll
    for (int k = 0; k < 4; k++) {
        int i = base4 + k;
        if (i < NN) {
            int o = start + loc[k];
            d_off[i] = o;
            d_cur[i] = o + 1;                 // edges go after the self entry
            d_src[o] = i;                     // self loop
            float di = rsqrtf((float)(d_cnt[i] + 1));
            d_dis[i] = di;
            float4 xv = ((const float4*)x)[i];
            d_xs[i] = make_float4(di * xv.x, di * xv.y, di * xv.z, di * xv.w);
        }
    }
}

// ---------------- K3: bucket edges into CSR ----------------
__global__ void k_bucket(const int* __restrict__ ei) {
    int e = blockIdx.x * blockDim.x + threadIdx.x;
    if (e >= NE) return;
    int r = ei[e];
    int c = ei[NE + e];
    int pos = atomicAdd(&d_cur[c], 1);
    d_src[pos] = r;
}

// ---------------- K4: layer-1 gather + W1 GEMM + relu, store h1s fp16 ----------------
// 4 lanes per node, 8 nodes per warp, 64 nodes per block.
__global__ void k_aggx_h1(const float* __restrict__ W1, const float* __restrict__ b1) {
    __shared__ float W1s[FXD][H];
    __shared__ float b1s[H];
    int tid = threadIdx.x;                    // 256
    if (tid < FXD * H) W1s[tid >> 6][tid & 63] = W1[tid];
    if (tid < H) b1s[tid] = b1[tid];
    __syncthreads();

    int w = tid >> 5;
    int lane = tid & 31;
    int grp = lane >> 2;                      // node group within warp (0..7)
    int sub = lane & 3;                       // lane within group
    int i = blockIdx.x * 64 + w * 8 + grp;    // node

    float4 acc = make_float4(0.f, 0.f, 0.f, 0.f);
    int off = 0, cnt = 0;
    if (i < NN) { off = d_off[i]; cnt = d_cnt[i] + 1; }
    for (int j = sub; j < cnt; j += 4) {
        int r = d_src[off + j];
        float4 t = d_xs[r];
        acc.x += t.x; acc.y += t.y; acc.z += t.z; acc.w += t.w;
    }
    // butterfly over the 4-lane group (stays within group for offsets 1, 2)
#pragma unroll
    for (int o = 1; o <= 2; o <<= 1) {
        acc.x += __shfl_xor_sync(0xffffffffu, acc.x, o);
        acc.y += __shfl_xor_sync(0xffffffffu, acc.y, o);
        acc.z += __shfl_xor_sync(0xffffffffu, acc.z, o);
        acc.w += __shfl_xor_sync(0xffffffffu, acc.w, o);
    }
    if (i >= NN) return;
    float di = d_dis[i];
    float4 v = make_float4(di * acc.x, di * acc.y, di * acc.z, di * acc.w);

    // each lane computes 16 output features of its node
    __half2 outh[8];
    int fb = sub * 16;
#pragma unroll
    for (int t = 0; t < 8; t++) {
        int f = fb + 2 * t;
        float h0 = b1s[f]   + v.x * W1s[0][f]   + v.y * W1s[1][f]   + v.z * W1s[2][f]   + v.w * W1s[3][f];
        float h1 = b1s[f+1] + v.x * W1s[0][f+1] + v.y * W1s[1][f+1] + v.z * W1s[2][f+1] + v.w * W1s[3][f+1];
        h0 = fmaxf(h0, 0.f) * di;
        h1 = fmaxf(h1, 0.f) * di;
        outh[t] = __floats2half2_rn(h0, h1);
    }
    uint4* dst = (uint4*)(d_h1s + (size_t)i * H + fb);
    dst[0] = ((const uint4*)outh)[0];
    dst[1] = ((const uint4*)outh)[1];
}

// ---------------- K5: layer-2 gather + W2 GEMM + pooled max (16 nodes/block) ----------
__global__ void k_fused(const float* __restrict__ W2, const float* __restrict__ b2,
                        const int* __restrict__ batch) {
    __shared__ __align__(16) float vt[H][20];   // [k][node], 16 nodes + pad
    int tid = threadIdx.x;                      // 256
    int i0 = blockIdx.x * 16;                   // 6250 blocks

    {   // phase 1: warp per 2 nodes, 4-wide unrolled gather
        int w = tid >> 5;
        int lane = tid & 31;
        const __half2* h1s2 = (const __half2*)d_h1s;
#pragma unroll
        for (int sub = 0; sub < 2; sub++) {
            int n = w * 2 + sub;
            int i = i0 + n;
            int off = d_off[i];
            int cnt = d_cnt[i] + 1;
            float ax0 = 0.f, ay0 = 0.f, ax1 = 0.f, ay1 = 0.f;
            int t = 0;
            for (; t + 4 <= cnt; t += 4) {
                int r0 = __ldg(&d_src[off + t]);
                int r1 = __ldg(&d_src[off + t + 1]);
                int r2 = __ldg(&d_src[off + t + 2]);
                int r3 = __ldg(&d_src[off + t + 3]);
                float2 f0 = __half22float2(h1s2[r0 * 32 + lane]);
                float2 f1 = __half22float2(h1s2[r1 * 32 + lane]);
                float2 f2 = __half22float2(h1s2[r2 * 32 + lane]);
                float2 f3 = __half22float2(h1s2[r3 * 32 + lane]);
                ax0 += f0.x + f2.x; ay0 += f0.y + f2.y;
                ax1 += f1.x + f3.x; ay1 += f1.y + f3.y;
            }
            for (; t < cnt; t++) {
                int r0 = __ldg(&d_src[off + t]);
                float2 f0 = __half22float2(h1s2[r0 * 32 + lane]);
                ax0 += f0.x; ay0 += f0.y;
            }
            float di = d_dis[i];
            vt[2 * lane][n]     = di * (ax0 + ax1);
            vt[2 * lane + 1][n] = di * (ay0 + ay1);
        }
    }
    __syncthreads();

    // phase 2: GEMM, f = tid&127, half = tid>>7 handles 8 nodes
    int f = tid & 127;
    int half = tid >> 7;
    float bb = b2[f];
    unsigned long long a01 = pack2(bb, bb), a23 = a01, a45 = a01, a67 = a01;
#pragma unroll
    for (int k = 0; k < H; k++) {
        float wv = __ldg(&W2[k * H2 + f]);
        unsigned long long wd = pack2(wv, wv);
        const ulonglong2* P = (const ulonglong2*)&vt[k][half * 8];
        ulonglong2 p0 = P[0];
        ulonglong2 p1 = P[1];
        a01 = fma2(p0.x, wd, a01);
        a23 = fma2(p0.y, wd, a23);
        a45 = fma2(p1.x, wd, a45);
        a67 = fma2(p1.y, wd, a67);
    }
    float2 r01 = unpack2(a01), r23 = unpack2(a23), r45 = unpack2(a45), r67 = unpack2(a67);
    float h[8] = { r01.x, r01.y, r23.x, r23.y, r45.x, r45.y, r67.x, r67.y };

    int bA = batch[i0];
    int bB = batch[i0 + 15];
    float mA = -1.f, mB = -1.f;
#pragma unroll
    for (int n = 0; n < 8; n++) {
        float hv = fmaxf(h[n], 0.f);
        if (batch[i0 + half * 8 + n] == bA) mA = fmaxf(mA, hv); else mB = fmaxf(mB, hv);
    }
    atomicMax(&d_gbits[bA * H2 + f], __float_as_int(mA));   // -1 bits are negative: no-op
    if (bB != bA) atomicMax(&d_gbits[bB * H2 + f], __float_as_int(mB));
}

// ---------------- K6: fused final MLPs + scratch re-zero for graph replay ----------------
__global__ void k_final(const float* __restrict__ Wg, const float* __restrict__ bg,
                        const float* __restrict__ Wt, const float* __restrict__ bt,
                        const float* __restrict__ Wf, const float* __restrict__ bf,
                        const float* __restrict__ Wo, const float* __restrict__ bo,
                        float* __restrict__ out) {
    __shared__ float sg[H2], st[H], sxc[H2], sy[H];
    int g = blockIdx.x;
    int f = threadIdx.x;                    // 64
    sg[f]      = __int_as_float(d_gbits[g * H2 + f]);
    sg[H + f]  = __int_as_float(d_gbits[g * H2 + H + f]);
    st[f]      = d_tmax[g * H + f];
    // re-zero own gbits slice for next replay (only this block reads it)
    d_gbits[g * H2 + f] = 0;
    d_gbits[g * H2 + H + f] = 0;
    // re-zero d_cnt strided and d_bsum (scan flags) for next replay
    for (int i = g * 64 + f; i < NN; i += NG * 64) d_cnt[i] = 0;
    {
        int gi = g * 64 + f;
        if (gi < NBLK) d_bsum[gi] = 0;
    }
    __syncthreads();

    float gg = bg[f];
#pragma unroll 8
    for (int j = 0; j < H2; j++) gg += sg[j] * Wg[j * H + f];
    float tt = bt[f];
#pragma unroll 8
    for (int j = 0; j < H; j++) tt += st[j] * Wt[j * H + f];
    sxc[f] = gg;
    sxc[H + f] = tt;
    __syncthreads();

    float y = bf[f];
#pragma unroll 8
    for (int j = 0; j < H2; j++) y += sxc[j] * Wf[j * H + f];
    sy[f] = fmaxf(y, 0.f);
    __syncthreads();

    if (f < NOUT) {
        float o = bo[f];
#pragma unroll 8
        for (int j = 0; j < H; j++) o += sy[j] * Wo[j * NOUT + f];
        out[g * NOUT + f] = o;
    }
}

// ---------------- launch ----------------
extern "C" void kernel_launch(void* const* d_in, const int* in_sizes, int n_in,
                              void* d_out, int out_size) {
    const float* x      = (const float*)d_in[0];
    const int*   ei     = (const int*)d_in[1];
    const int*   batch  = (const int*)d_in[2];
    const float* target = (const float*)d_in[3];
    const float* W1 = (const float*)d_in[4];
    const float* b1 = (const float*)d_in[5];
    const float* W2 = (const float*)d_in[6];
    const float* b2 = (const float*)d_in[7];
    const float* Wg = (const float*)d_in[8];
    const float* bg = (const float*)d_in[9];
    const float* Wc = (const float*)d_in[10];
    const float* bc = (const float*)d_in[11];
    const float* Wt = (const float*)d_in[12];
    const float* bt = (const float*)d_in[13];
    const float* Wf = (const float*)d_in[14];
    const float* bf = (const float*)d_in[15];
    const float* Wo = (const float*)d_in[16];
    const float* bo = (const float*)d_in[17];
    float* out = (float*)d_out;

    k_histconv<<<NG + HISTB, 256>>>(ei, target, Wc, bc);
    k_scan<<<NBLK, 256>>>(x);
    k_bucket<<<(NE + 255) / 256, 256>>>(ei);
    k_aggx_h1<<<(NN + 63) / 64, 256>>>(W1, b1);
    k_fused<<<NN / 16, 256>>>(W2, b2, batch);
    k_final<<<NG, 64>>>(Wg, bg, Wt, bt, Wf, bf, Wo, bo, out);
}

// round 16
// speedup vs baseline: 1.1741x; 1.0014x over previous
#include <cuda_runtime.h>
#include <cuda_fp16.h>
#include <cstdint>

#define NN  100000
#define NE  1600000
#define NG  512
#define LL  1000
#define FXD 4
#define FXT 5
#define H   64
#define H2  128
#define NOUT 2
#define NBLK 98          // ceil(NN/1024) scan blocks (one wave, <=148 SMs)
#define HISTB ((NE + 1023) / 1024)   // hist blocks (4 edges/thread)

// ---------------- scratch (zero at load; k_final re-zeroes what must be zero) ----------------
__device__ int    d_cnt[NN];           // in-degree (edges only; +1 self added logically)
__device__ int    d_off[NN];           // CSR offsets (incl. self)
__device__ int    d_cur[NN];           // bucket cursors
__device__ int    d_bsum[NBLK];        // block totals; nonzero doubles as ready flag
__device__ int    d_src[NE + NN];      // CSR source list (self at off[i], edges after)
__device__ float  d_dis[NN];
__device__ float4 d_xs[NN];            // dis[i] * x[i]
__device__ __half d_h1s[NN * H];       // dis[i] * relu-h1[i], fp16
__device__ int    d_gbits[NG * H2];    // pooled max(h2) as ordered int bits
__device__ float  d_tmax[NG * H];      // conv1d branch pooled output

__device__ __forceinline__ unsigned long long fma2(unsigned long long a,
                                                   unsigned long long b,
                                                   unsigned long long c) {
    unsigned long long d;
    asm("fma.rn.f32x2 %0, %1, %2, %3;" : "=l"(d) : "l"(a), "l"(b), "l"(c));
    return d;
}
__device__ __forceinline__ unsigned long long pack2(float a, float b) {
    unsigned long long d;
    asm("mov.b64 %0, {%1,%2};" : "=l"(d) : "f"(a), "f"(b));
    return d;
}
__device__ __forceinline__ float2 unpack2(unsigned long long a) {
    float2 r;
    asm("mov.b64 {%0,%1}, %2;" : "=f"(r.x), "=f"(r.y) : "l"(a));
    return r;
}

// ---------------- K1: blocks [0,NG): conv1d branch; blocks [NG,...): degree histogram ----
__global__ void k_histconv(const int* __restrict__ ei,
                           const float* __restrict__ target,
                           const float* __restrict__ Wc, const float* __restrict__ bc) {
    __shared__ __align__(16) char s_raw[25088];
    int tid = threadIdx.x;                    // 256

    if (blockIdx.x >= NG) {
        // ---- histogram: 4 edges per thread over the col half of ei ----
        int e = (blockIdx.x - NG) * 1024 + tid * 4;
        if (e + 4 <= NE) {
            int4 c4 = *(const int4*)(ei + NE + e);
            atomicAdd(&d_cnt[c4.x], 1);
            atomicAdd(&d_cnt[c4.y], 1);
            atomicAdd(&d_cnt[c4.z], 1);
            atomicAdd(&d_cnt[c4.w], 1);
        } else {
            for (int k = 0; k < 4 && e + k < NE; k++)
                atomicAdd(&d_cnt[ei[NE + e + k]], 1);
        }
        return;
    }

    // ---- conv1d branch ----
    float (*sh)[6] = (float(*)[6])s_raw;          // [LL][6], col 5 = zero pad
    float* red = (float*)(s_raw + 24000);         // [256]
    int g = blockIdx.x;
    const float* tg = target + (size_t)g * LL * FXT;
    for (int idx = tid; idx < LL * FXT; idx += 256) {
        int l = idx / FXT, i = idx - l * FXT;
        sh[l][i] = tg[idx];
    }
    for (int l = tid; l < LL; l += 256) sh[l][5] = 0.f;
    __syncthreads();

    int c   = tid & 63;
    int seg = tid >> 6;
    unsigned long long wk[3][3];
#pragma unroll
    for (int k = 0; k < 3; k++)
#pragma unroll
        for (int p = 0; p < 3; p++) {
            float w0 = Wc[c * 15 + (2 * p) * 3 + k];
            float w1 = (p < 2) ? Wc[c * 15 + (2 * p + 1) * 3 + k] : 0.f;
            wk[k][p] = pack2(w0, w1);
        }

    int start = seg * 250;
    int end = (seg == 3) ? (LL - 2) : (start + 250);
    float m = -3.4e38f;
    for (int l = start; l < end; l++) {
        unsigned long long a0 = 0ull, a1 = 0ull, a2 = 0ull;
#pragma unroll
        for (int k = 0; k < 3; k++) {
            const unsigned long long* row = (const unsigned long long*)&sh[l + k][0];
            a0 = fma2(row[0], wk[k][0], a0);
            a1 = fma2(row[1], wk[k][1], a1);
            a2 = fma2(row[2], wk[k][2], a2);
        }
        float2 f0 = unpack2(a0), f1 = unpack2(a1), f2 = unpack2(a2);
        m = fmaxf(m, (f0.x + f0.y) + (f1.x + f1.y) + (f2.x + f2.y));
    }
    red[tid] = m;
    __syncthreads();
    if (seg == 0) {
        m = fmaxf(fmaxf(red[c], red[64 + c]), fmaxf(red[128 + c], red[192 + c]));
        m += bc[c];
        d_tmax[g * H + c] = fmaxf(m, 0.f);
    }
}

// ---------------- K2: single-pass scan (decoupled prefix) -> offsets, cursors, self, dis, xs
__global__ void k_scan(const float* __restrict__ x) {
    __shared__ int tsum[256];
    __shared__ int sh_base;
    int b = blockIdx.x, tid = threadIdx.x;
    int base4 = b * 1024 + tid * 4;
    int loc[4]; int s = 0;
#pragma unroll
    for (int k = 0; k < 4; k++) {
        int i = base4 + k;
        int v = (i < NN) ? (d_cnt[i] + 1) : 0;
        loc[k] = s; s += v;
    }
    tsum[tid] = s; __syncthreads();
    for (int o = 1; o < 256; o <<= 1) {
        int y = (tid >= o) ? tsum[tid - o] : 0;
        __syncthreads();
        tsum[tid] += y;
        __syncthreads();
    }
    // publish this block's total (nonzero: every node contributes >=1)
    if (tid == 0) *(volatile int*)&d_bsum[b] = tsum[255];
    // warp 0 spins on predecessors to get exclusive base
    if (tid < 32) {
        int acc = 0;
        for (int p = tid; p < b; p += 32) {
            int v;
            do { v = *(volatile int*)&d_bsum[p]; } while (v == 0);
            acc += v;
        }
#pragma unroll
        for (int o = 16; o; o >>= 1) acc += __shfl_xor_sync(0xffffffffu, acc, o);
        if (tid == 0) sh_base = acc;
    }
    __syncthreads();
    int start = sh_base + tsum[tid] - s;      // exclusive prefix for this thread's 4 nodes
#pragma unroll
    for (int k = 0; k < 4; k++) {
        int i = base4 + k;
        if (i < NN) {
            int o = start + loc[k];
            d_off[i] = o;
            d_cur[i] = o + 1;                 // edges go after the self entry
            d_src[o] = i;                     // self loop
            float di = rsqrtf((float)(d_cnt[i] + 1));
            d_dis[i] = di;
            float4 xv = ((const float4*)x)[i];
            d_xs[i] = make_float4(di * xv.x, di * xv.y, di * xv.z, di * xv.w);
        }
    }
}

// ---------------- K3: bucket edges into CSR ----------------
__global__ void k_bucket(const int* __restrict__ ei) {
    int e = blockIdx.x * blockDim.x + threadIdx.x;
    if (e >= NE) return;
    int r = ei[e];
    int c = ei[NE + e];
    int pos = atomicAdd(&d_cur[c], 1);
    d_src[pos] = r;
}

// ---------------- K4: layer-1 gather + W1 GEMM + relu, store h1s fp16 ----------------
// 4 lanes per node, 8 nodes per warp, 64 nodes per block, 2-wide unrolled gather.
__global__ void k_aggx_h1(const float* __restrict__ W1, const float* __restrict__ b1) {
    __shared__ float W1s[FXD][H];
    __shared__ float b1s[H];
    int tid = threadIdx.x;                    // 256
    if (tid < FXD * H) W1s[tid >> 6][tid & 63] = W1[tid];
    if (tid < H) b1s[tid] = b1[tid];
    __syncthreads();

    int w = tid >> 5;
    int lane = tid & 31;
    int grp = lane >> 2;                      // node group within warp (0..7)
    int sub = lane & 3;                       // lane within group
    int i = blockIdx.x * 64 + w * 8 + grp;    // node

    float4 acc = make_float4(0.f, 0.f, 0.f, 0.f);
    float4 acc2 = make_float4(0.f, 0.f, 0.f, 0.f);
    int off = 0, cnt = 0;
    if (i < NN) { off = d_off[i]; cnt = d_cnt[i] + 1; }
    int j = sub;
    for (; j + 4 < cnt; j += 8) {
        int r0 = d_src[off + j];
        int r1 = d_src[off + j + 4];
        float4 t0 = d_xs[r0];
        float4 t1 = d_xs[r1];
        acc.x += t0.x; acc.y += t0.y; acc.z += t0.z; acc.w += t0.w;
        acc2.x += t1.x; acc2.y += t1.y; acc2.z += t1.z; acc2.w += t1.w;
    }
    if (j < cnt) {
        int r0 = d_src[off + j];
        float4 t0 = d_xs[r0];
        acc.x += t0.x; acc.y += t0.y; acc.z += t0.z; acc.w += t0.w;
    }
    acc.x += acc2.x; acc.y += acc2.y; acc.z += acc2.z; acc.w += acc2.w;
    // butterfly over the 4-lane group (stays within group for offsets 1, 2)
#pragma unroll
    for (int o = 1; o <= 2; o <<= 1) {
        acc.x += __shfl_xor_sync(0xffffffffu, acc.x, o);
        acc.y += __shfl_xor_sync(0xffffffffu, acc.y, o);
        acc.z += __shfl_xor_sync(0xffffffffu, acc.z, o);
        acc.w += __shfl_xor_sync(0xffffffffu, acc.w, o);
    }
    if (i >= NN) return;
    float di = d_dis[i];
    float4 v = make_float4(di * acc.x, di * acc.y, di * acc.z, di * acc.w);

    // each lane computes 16 output features of its node
    __half2 outh[8];
    int fb = sub * 16;
#pragma unroll
    for (int t = 0; t < 8; t++) {
        int f = fb + 2 * t;
        float h0 = b1s[f]   + v.x * W1s[0][f]   + v.y * W1s[1][f]   + v.z * W1s[2][f]   + v.w * W1s[3][f];
        float h1 = b1s[f+1] + v.x * W1s[0][f+1] + v.y * W1s[1][f+1] + v.z * W1s[2][f+1] + v.w * W1s[3][f+1];
        h0 = fmaxf(h0, 0.f) * di;
        h1 = fmaxf(h1, 0.f) * di;
        outh[t] = __floats2half2_rn(h0, h1);
    }
    uint4* dst = (uint4*)(d_h1s + (size_t)i * H + fb);
    dst[0] = ((const uint4*)outh)[0];
    dst[1] = ((const uint4*)outh)[1];
}

// ---------------- K5: layer-2 gather + W2 GEMM + pooled max (16 nodes/block) ----------
// Phase 1 interleaves the warp's two nodes for 8 outstanding gathers.
__global__ void k_fused(const float* __restrict__ W2, const float* __restrict__ b2,
                        const int* __restrict__ batch) {
    __shared__ __align__(16) float vt[H][20];   // [k][node], 16 nodes + pad
    int tid = threadIdx.x;                      // 256
    int i0 = blockIdx.x * 16;                   // 6250 blocks

    {   // phase 1: warp per 2 nodes, interleaved 4+4 gather
        int w = tid >> 5;
        int lane = tid & 31;
        const __half2* h1s2 = (const __half2*)d_h1s;
        int iA = i0 + w * 2;
        int iB = iA + 1;
        int offA = d_off[iA], cntA = d_cnt[iA] + 1;
        int offB = d_off[iB], cntB = d_cnt[iB] + 1;
        float axA0 = 0.f, ayA0 = 0.f, axA1 = 0.f, ayA1 = 0.f;
        float axB0 = 0.f, ayB0 = 0.f, axB1 = 0.f, ayB1 = 0.f;
        int m = min(cntA, cntB);
        int t = 0;
        for (; t + 4 <= m; t += 4) {
            int rA0 = __ldg(&d_src[offA + t]);
            int rA1 = __ldg(&d_src[offA + t + 1]);
            int rA2 = __ldg(&d_src[offA + t + 2]);
            int rA3 = __ldg(&d_src[offA + t + 3]);
            int rB0 = __ldg(&d_src[offB + t]);
            int rB1 = __ldg(&d_src[offB + t + 1]);
            int rB2 = __ldg(&d_src[offB + t + 2]);
            int rB3 = __ldg(&d_src[offB + t + 3]);
            float2 fA0 = __half22float2(h1s2[rA0 * 32 + lane]);
            float2 fA1 = __half22float2(h1s2[rA1 * 32 + lane]);
            float2 fA2 = __half22float2(h1s2[rA2 * 32 + lane]);
            float2 fA3 = __half22float2(h1s2[rA3 * 32 + lane]);
            float2 fB0 = __half22float2(h1s2[rB0 * 32 + lane]);
            float2 fB1 = __half22float2(h1s2[rB1 * 32 + lane]);
            float2 fB2 = __half22float2(h1s2[rB2 * 32 + lane]);
            float2 fB3 = __half22float2(h1s2[rB3 * 32 + lane]);
            axA0 += fA0.x + fA2.x; ayA0 += fA0.y + fA2.y;
            axA1 += fA1.x + fA3.x; ayA1 += fA1.y + fA3.y;
            axB0 += fB0.x + fB2.x; ayB0 += fB0.y + fB2.y;
            axB1 += fB1.x + fB3.x; ayB1 += fB1.y + fB3.y;
        }
        // tail A
        {
            int tt = t;
            for (; tt + 4 <= cntA; tt += 4) {
                int r0 = __ldg(&d_src[offA + tt]);
                int r1 = __ldg(&d_src[offA + tt + 1]);
                int r2 = __ldg(&d_src[offA + tt + 2]);
                int r3 = __ldg(&d_src[offA + tt + 3]);
                float2 f0 = __half22float2(h1s2[r0 * 32 + lane]);
                float2 f1 = __half22float2(h1s2[r1 * 32 + lane]);
                float2 f2 = __half22float2(h1s2[r2 * 32 + lane]);
                float2 f3 = __half22float2(h1s2[r3 * 32 + lane]);
                axA0 += f0.x + f2.x; ayA0 += f0.y + f2.y;
                axA1 += f1.x + f3.x; ayA1 += f1.y + f3.y;
            }
            for (; tt < cntA; tt++) {
                int r0 = __ldg(&d_src[offA + tt]);
                float2 f0 = __half22float2(h1s2[r0 * 32 + lane]);
                axA0 += f0.x; ayA0 += f0.y;
            }
        }
        // tail B
        {
            int tt = t;
            for (; tt + 4 <= cntB; tt += 4) {
                int r0 = __ldg(&d_src[offB + tt]);
                int r1 = __ldg(&d_src[offB + tt + 1]);
                int r2 = __ldg(&d_src[offB + tt + 2]);
                int r3 = __ldg(&d_src[offB + tt + 3]);
                float2 f0 = __half22float2(h1s2[r0 * 32 + lane]);
                float2 f1 = __half22float2(h1s2[r1 * 32 + lane]);
                float2 f2 = __half22float2(h1s2[r2 * 32 + lane]);
                float2 f3 = __half22float2(h1s2[r3 * 32 + lane]);
                axB0 += f0.x + f2.x; ayB0 += f0.y + f2.y;
                axB1 += f1.x + f3.x; ayB1 += f1.y + f3.y;
            }
            for (; tt < cntB; tt++) {
                int r0 = __ldg(&d_src[offB + tt]);
                float2 f0 = __half22float2(h1s2[r0 * 32 + lane]);
                axB0 += f0.x; ayB0 += f0.y;
            }
        }
        float diA = d_dis[iA];
        float diB = d_dis[iB];
        int nA = w * 2, nB = nA + 1;
        vt[2 * lane][nA]     = diA * (axA0 + axA1);
        vt[2 * lane + 1][nA] = diA * (ayA0 + ayA1);
        vt[2 * lane][nB]     = diB * (axB0 + axB1);
        vt[2 * lane + 1][nB] = diB * (ayB0 + ayB1);
    }
    __syncthreads();

    // phase 2: GEMM, f = tid&127, half = tid>>7 handles 8 nodes
    int f = tid & 127;
    int half = tid >> 7;
    float bb = b2[f];
    unsigned long long a01 = pack2(bb, bb), a23 = a01, a45 = a01, a67 = a01;
#pragma unroll
    for (int k = 0; k < H; k++) {
        float wv = __ldg(&W2[k * H2 + f]);
        unsigned long long wd = pack2(wv, wv);
        const ulonglong2* P = (const ulonglong2*)&vt[k][half * 8];
        ulonglong2 p0 = P[0];
        ulonglong2 p1 = P[1];
        a01 = fma2(p0.x, wd, a01);
        a23 = fma2(p0.y, wd, a23);
        a45 = fma2(p1.x, wd, a45);
        a67 = fma2(p1.y, wd, a67);
    }
    float2 r01 = unpack2(a01), r23 = unpack2(a23), r45 = unpack2(a45), r67 = unpack2(a67);
    float h[8] = { r01.x, r01.y, r23.x, r23.y, r45.x, r45.y, r67.x, r67.y };

    int bA = batch[i0];
    int bB = batch[i0 + 15];
    float mA = -1.f, mB = -1.f;
#pragma unroll
    for (int n = 0; n < 8; n++) {
        float hv = fmaxf(h[n], 0.f);
        if (batch[i0 + half * 8 + n] == bA) mA = fmaxf(mA, hv); else mB = fmaxf(mB, hv);
    }
    atomicMax(&d_gbits[bA * H2 + f], __float_as_int(mA));   // -1 bits are negative: no-op
    if (bB != bA) atomicMax(&d_gbits[bB * H2 + f], __float_as_int(mB));
}

// ---------------- K6: fused final MLPs + scratch re-zero for graph replay ----------------
__global__ void k_final(const float* __restrict__ Wg, const float* __restrict__ bg,
                        const float* __restrict__ Wt, const float* __restrict__ bt,
                        const float* __restrict__ Wf, const float* __restrict__ bf,
                        const float* __restrict__ Wo, const float* __restrict__ bo,
                        float* __restrict__ out) {
    __shared__ float sg[H2], st[H], sxc[H2], sy[H];
    int g = blockIdx.x;
    int f = threadIdx.x;                    // 64
    sg[f]      = __int_as_float(d_gbits[g * H2 + f]);
    sg[H + f]  = __int_as_float(d_gbits[g * H2 + H + f]);
    st[f]      = d_tmax[g * H + f];
    // re-zero own gbits slice for next replay (only this block reads it)
    d_gbits[g * H2 + f] = 0;
    d_gbits[g * H2 + H + f] = 0;
    // re-zero d_cnt strided and d_bsum (scan flags) for next replay
    for (int i = g * 64 + f; i < NN; i += NG * 64) d_cnt[i] = 0;
    {
        int gi = g * 64 + f;
        if (gi < NBLK) d_bsum[gi] = 0;
    }
    __syncthreads();

    float gg = bg[f];
#pragma unroll 8
    for (int j = 0; j < H2; j++) gg += sg[j] * Wg[j * H + f];
    float tt = bt[f];
#pragma unroll 8
    for (int j = 0; j < H; j++) tt += st[j] * Wt[j * H + f];
    sxc[f] = gg;
    sxc[H + f] = tt;
    __syncthreads();

    float y = bf[f];
#pragma unroll 8
    for (int j = 0; j < H2; j++) y += sxc[j] * Wf[j * H + f];
    sy[f] = fmaxf(y, 0.f);
    __syncthreads();

    if (f < NOUT) {
        float o = bo[f];
#pragma unroll 8
        for (int j = 0; j < H; j++) o += sy[j] * Wo[j * NOUT + f];
        out[g * NOUT + f] = o;
    }
}

// ---------------- launch ----------------
extern "C" void kernel_launch(void* const* d_in, const int* in_sizes, int n_in,
                              void* d_out, int out_size) {
    const float* x      = (const float*)d_in[0];
    const int*   ei     = (const int*)d_in[1];
    const int*   batch  = (const int*)d_in[2];
    const float* target = (const float*)d_in[3];
    const float* W1 = (const float*)d_in[4];
    const float* b1 = (const float*)d_in[5];
    const float* W2 = (const float*)d_in[6];
    const float* b2 = (const float*)d_in[7];
    const float* Wg = (const float*)d_in[8];
    const float* bg = (const float*)d_in[9];
    const float* Wc = (const float*)d_in[10];
    const float* bc = (const float*)d_in[11];
    const float* Wt = (const float*)d_in[12];
    const float* bt = (const float*)d_in[13];
    const float* Wf = (const float*)d_in[14];
    const float* bf = (const float*)d_in[15];
    const float* Wo = (const float*)d_in[16];
    const float* bo = (const float*)d_in[17];
    float* out = (float*)d_out;

    k_histconv<<<NG + HISTB, 256>>>(ei, target, Wc, bc);
    k_scan<<<NBLK, 256>>>(x);
    k_bucket<<<(NE + 255) / 256, 256>>>(ei);
    k_aggx_h1<<<(NN + 63) / 64, 256>>>(W1, b1);
    k_fused<<<NN / 16, 256>>>(W2, b2, batch);
    k_final<<<NG, 64>>>(Wg, bg, Wt, bt, Wf, bf, Wo, bo, out);
}